// round 11
// baseline (speedup 1.0000x reference)
#include <cuda_runtime.h>
#include <cuda_fp16.h>
#include <cstdint>

// ---------------------------------------------------------------------------
// Attention_layer, R10: 3 CTAs/SM. x stored non-dup fp16 as half2(d,d+1) in
// [dp][c] layout (65-word padded rows, conflict-free); in-register dup via
// low2half2/high2half2. Union x|kqT = 1284 words/warp -> 67KB smem.
// launch_bounds(256,3) -> 80 regs. Rest of pipeline = R9.
// ---------------------------------------------------------------------------

__device__ __forceinline__ float ex2(float x) {
    float r; asm("ex2.approx.f32 %0,%1;" : "=f"(r) : "f"(x)); return r;
}

// Problem constants
static constexpr int B  = 8;
static constexpr int CH = 64;
static constexpr int D  = 32;
static constexpr int H  = 64;
static constexpr int W  = 64;
static constexpr int S  = 32;
static constexpr int WT = 8;            // positions (warps) per CTA
static constexpr int HW = H * W;

static constexpr int XROW = 65;         // x row stride in half2 (words), padded
static constexpr int RPH  = 40;         // kqT row stride in halves (32 + 8 pad)
static constexpr int QT_H = 1280;       // qT offset in halves
static constexpr int UW   = 1284;       // per-warp union (words): x(1040) | kqT(1280)

// smem layout (floats/words)
static constexpr int OFF_U    = 0;                    // 8 * 1284 = 10272
static constexpr int OFF_WKH  = OFF_U + WT * UW;      // 10272 (fp16 [c][s], 1024 w)
static constexpr int OFF_WQH  = OFF_WKH + 1024;
static constexpr int OFF_WVH  = OFF_WQH + 1024;
static constexpr int OFF_WOT  = OFF_WVH + 1024;       // fp32 [s][c] 2048
static constexpr int OFF_BH   = OFF_WOT + S * CH;     // fp16 biases (96 halves = 48w)
static constexpr int OFF_BO   = OFF_BH + 48;
static constexpr int OFF_MX   = OFF_BO + CH;          // x-mean [w][c] 512
static constexpr int OFF_AB   = OFF_MX + WT * CH;     // abar/om 8*32
static constexpr int OFF_OUT  = OFF_AB + WT * S;
static constexpr int SMEM_FLOATS = OFF_OUT + CH * WT; // 16784
static constexpr size_t SMEM_BYTES = (size_t)SMEM_FLOATS * 4;  // ~67.1 KB

__global__ __launch_bounds__(256, 3)
void attn_fused_kernel(const float* __restrict__ x,
                       const float* __restrict__ Wk, const float* __restrict__ bk,
                       const float* __restrict__ Wq, const float* __restrict__ bq,
                       const float* __restrict__ Wv, const float* __restrict__ bv,
                       const float* __restrict__ Wo, const float* __restrict__ bo,
                       const float* __restrict__ factor,
                       float* __restrict__ out)
{
    extern __shared__ float sm[];
    const int tid  = threadIdx.x;
    const int blk  = blockIdx.x;
    const int b    = blk >> 9;
    const int rem  = blk & 511;
    const int h    = rem >> 3;
    const int w0   = (rem & 7) << 3;

    // ---- Stage x: thread = (c, w-pair). fp32 mean accumulated in regs.
    //      x stored as half2(x_d, x_{d+1}) at [dp*65 + c] per w region. ----
    {
        const int c  = tid >> 2;          // 0..63
        const int wp = (tid & 3) << 1;    // 0,2,4,6
        const float* bi = x + ((size_t)b * CH * D + (size_t)c * D) * HW + h * W + w0 + wp;
        __half2* xhA = (__half2*)(sm + OFF_U + (size_t)wp * UW);
        __half2* xhB = (__half2*)(sm + OFF_U + (size_t)(wp + 1) * UW);
        float msA = 0.f, msB = 0.f;
        #pragma unroll 4
        for (int dp = 0; dp < 16; ++dp) {
            float2 v0 = *(const float2*)(bi + (size_t)(2 * dp) * HW);
            float2 v1 = *(const float2*)(bi + (size_t)(2 * dp + 1) * HW);
            msA += v0.x + v1.x; msB += v0.y + v1.y;
            xhA[dp * XROW + c] = __floats2half2_rn(v0.x, v1.x);
            xhB[dp * XROW + c] = __floats2half2_rn(v0.y, v1.y);
        }
        sm[OFF_MX + wp * CH + c]       = msA;
        sm[OFF_MX + (wp + 1) * CH + c] = msB;
    }

    // ---- Stage weights: Wk/Wq/Wv fp16 [c][s] (s-pairs packed) ----
    {
        __half2* wkh = (__half2*)(sm + OFF_WKH);
        __half2* wqh = (__half2*)(sm + OFF_WQH);
        __half2* wvh = (__half2*)(sm + OFF_WVH);
        for (int i = tid; i < 1024; i += 256) {
            int c = i >> 4, sp = i & 15, s2 = sp << 1;
            wkh[c * 16 + sp] = __floats2half2_rn(Wk[s2 * CH + c], Wk[(s2 + 1) * CH + c]);
            wqh[c * 16 + sp] = __floats2half2_rn(Wq[s2 * CH + c], Wq[(s2 + 1) * CH + c]);
            wvh[c * 16 + sp] = __floats2half2_rn(Wv[s2 * CH + c], Wv[(s2 + 1) * CH + c]);
        }
    }
    // Wo fp32 [s][c]
    for (int i = tid; i < CH * S; i += 256) {
        int s2 = i >> 6, c2 = i & 63;
        sm[OFF_WOT + i] = Wo[c2 * S + s2];
    }
    // biases fp16 (pairs)
    if (tid < 48) {
        int m = tid >> 4, t = tid & 15;
        const float* bsrc = (m == 0) ? bk : ((m == 1) ? bq : bv);
        ((__half2*)(sm + OFF_BH))[m * 16 + t] = __floats2half2_rn(bsrc[2 * t], bsrc[2 * t + 1]);
    }
    if (tid < CH) sm[OFF_BO + tid] = bo[tid];
    __syncthreads();

    const int warp = tid >> 5;
    const int lane = tid & 31;
    // scores-phase decomposition
    const int sg   = lane >> 3;   // 0..3
    const int jg   = lane & 7;    // 0..7
    // projection-phase decomposition
    const int sgrp = lane >> 2;   // 0..7 : s = sgrp*4 .. +3
    const int dgrp = lane & 3;    // 0..3 : d = dgrp*8 .. +7

    const __half2* xh2 = (const __half2*)(sm + OFF_U + warp * UW); // [dp][c]
    __half* kTh = (__half*)(sm + OFF_U + warp * UW);               // aliases x (dead)
    __half* qTh = kTh + QT_H;
    float*  ABARw = sm + OFF_AB + warp * S;

    // ============== Merged projections k,q,v: one sweep over c =============
    // accum: half2 packed over s-pair; lane tile 4s x 8d
    __half2 acK[2][8], acQ[2][8], acV[2][8];
    {
        const __half* bh = (const __half*)(sm + OFF_BH);
        uint2 bkp = *(const uint2*)(bh + sgrp * 4);
        uint2 bqp = *(const uint2*)(bh + 32 + sgrp * 4);
        uint2 bvp = *(const uint2*)(bh + 64 + sgrp * 4);
        __half2 bk0 = *(__half2*)&bkp.x, bk1 = *(__half2*)&bkp.y;
        __half2 bq0 = *(__half2*)&bqp.x, bq1 = *(__half2*)&bqp.y;
        __half2 bv0 = *(__half2*)&bvp.x, bv1 = *(__half2*)&bvp.y;
        #pragma unroll
        for (int dd = 0; dd < 8; ++dd) {
            acK[0][dd] = bk0; acK[1][dd] = bk1;
            acQ[0][dd] = bq0; acQ[1][dd] = bq1;
            acV[0][dd] = bv0; acV[1][dd] = bv1;
        }
    }
    {
        const __half* wkh = (const __half*)(sm + OFF_WKH);
        const __half* wqh = (const __half*)(sm + OFF_WQH);
        const __half* wvh = (const __half*)(sm + OFF_WVH);
        const int xrow = dgrp * 4;
        #pragma unroll 2
        for (int c = 0; c < CH; ++c) {
            // 4 x half2 pairs (d-pairs) for this lane's d-block, conflict-free
            __half2 p0 = xh2[(xrow + 0) * XROW + c];
            __half2 p1 = xh2[(xrow + 1) * XROW + c];
            __half2 p2 = xh2[(xrow + 2) * XROW + c];
            __half2 p3 = xh2[(xrow + 3) * XROW + c];
            // 4 s-values per matrix (1 x LDS.64 each)
            uint2 wkr = *(const uint2*)(wkh + c * 32 + sgrp * 4);
            uint2 wqr = *(const uint2*)(wqh + c * 32 + sgrp * 4);
            uint2 wvr = *(const uint2*)(wvh + c * 32 + sgrp * 4);
            __half2 wk0 = *(__half2*)&wkr.x, wk1 = *(__half2*)&wkr.y;
            __half2 wq0 = *(__half2*)&wqr.x, wq1 = *(__half2*)&wqr.y;
            __half2 wv0 = *(__half2*)&wvr.x, wv1 = *(__half2*)&wvr.y;
            __half2 xd[8];
            xd[0] = __low2half2(p0); xd[1] = __high2half2(p0);
            xd[2] = __low2half2(p1); xd[3] = __high2half2(p1);
            xd[4] = __low2half2(p2); xd[5] = __high2half2(p2);
            xd[6] = __low2half2(p3); xd[7] = __high2half2(p3);
            #pragma unroll
            for (int dd = 0; dd < 8; ++dd) {
                acK[0][dd] = __hfma2(wk0, xd[dd], acK[0][dd]);
                acK[1][dd] = __hfma2(wk1, xd[dd], acK[1][dd]);
                acQ[0][dd] = __hfma2(wq0, xd[dd], acQ[0][dd]);
                acQ[1][dd] = __hfma2(wq1, xd[dd], acQ[1][dd]);
                acV[0][dd] = __hfma2(wv0, xd[dd], acV[0][dd]);
                acV[1][dd] = __hfma2(wv1, xd[dd], acV[1][dd]);
            }
        }
    }
    __syncwarp();
    // x dead -> store kT/qT [d][s] fp16 (s-contiguous, matches phase B)
    #pragma unroll
    for (int dd = 0; dd < 8; ++dd) {
        int d = dgrp * 8 + dd;
        uint2 kst; kst.x = *(unsigned*)&acK[0][dd]; kst.y = *(unsigned*)&acK[1][dd];
        uint2 qst; qst.x = *(unsigned*)&acQ[0][dd]; qst.y = *(unsigned*)&acQ[1][dd];
        *(uint2*)(kTh + d * RPH + sgrp * 4) = kst;
        *(uint2*)(qTh + d * RPH + sgrp * 4) = qst;
    }
    __syncwarp();

    // ================= Phase B: scores[i][j] = sum_s k[s][i] q[s][j] =======
    // i = 4*ti + sg, j = 8*tj + jg ; fp16 HFMA2, accum packed over s-pairs
    __half2 acc[8][4];
    {
        __half2 z = __float2half2_rn(0.f);
        #pragma unroll
        for (int ti = 0; ti < 8; ++ti)
            #pragma unroll
            for (int tj = 0; tj < 4; ++tj) acc[ti][tj] = z;
    }
    #pragma unroll
    for (int ch = 0; ch < 4; ++ch) {
        uint4 qqr[4];
        #pragma unroll
        for (int tj = 0; tj < 4; ++tj)
            qqr[tj] = *(const uint4*)(qTh + (8 * tj + jg) * RPH + ch * 8);
        #pragma unroll
        for (int ti = 0; ti < 8; ++ti) {
            uint4 kkr = *(const uint4*)(kTh + (4 * ti + sg) * RPH + ch * 8);
            const __half2* kh = (const __half2*)&kkr;
            #pragma unroll
            for (int tj = 0; tj < 4; ++tj) {
                const __half2* qh = (const __half2*)&qqr[tj];
                acc[ti][tj] = __hfma2(kh[0], qh[0], acc[ti][tj]);
                acc[ti][tj] = __hfma2(kh[1], qh[1], acc[ti][tj]);
                acc[ti][tj] = __hfma2(kh[2], qh[2], acc[ti][tj]);
                acc[ti][tj] = __hfma2(kh[3], qh[3], acc[ti][tj]);
            }
        }
    }
    float sc[8][4];
    #pragma unroll
    for (int ti = 0; ti < 8; ++ti)
        #pragma unroll
        for (int tj = 0; tj < 4; ++tj)
            sc[ti][tj] = __low2float(acc[ti][tj]) + __high2float(acc[ti][tj]);

    // ================= Phase C: softmax over i (per column j), fp32 ========
    const float CEXP = 0.17677669529663687f * 1.44269504088896340f;
    #pragma unroll
    for (int tj = 0; tj < 4; ++tj) {
        float m = sc[0][tj];
        #pragma unroll
        for (int ti = 1; ti < 8; ++ti) m = fmaxf(m, sc[ti][tj]);
        m = fmaxf(m, __shfl_xor_sync(0xffffffffu, m, 8));
        m = fmaxf(m, __shfl_xor_sync(0xffffffffu, m, 16));
        float sum = 0.f;
        #pragma unroll
        for (int ti = 0; ti < 8; ++ti) {
            float e = ex2((sc[ti][tj] - m) * CEXP);
            sc[ti][tj] = e; sum += e;
        }
        sum += __shfl_xor_sync(0xffffffffu, sum, 8);
        sum += __shfl_xor_sync(0xffffffffu, sum, 16);
        float r = 1.0f / sum;
        #pragma unroll
        for (int ti = 0; ti < 8; ++ti) sc[ti][tj] *= r;
    }

    // ---- abar[i] = (1/32) * sum_j a[i][j] ----
    float ab[8];
    #pragma unroll
    for (int ti = 0; ti < 8; ++ti)
        ab[ti] = (sc[ti][0] + sc[ti][1]) + (sc[ti][2] + sc[ti][3]);
    #pragma unroll
    for (int ti = 0; ti < 8; ++ti) {
        ab[ti] += __shfl_xor_sync(0xffffffffu, ab[ti], 1);
        ab[ti] += __shfl_xor_sync(0xffffffffu, ab[ti], 2);
        ab[ti] += __shfl_xor_sync(0xffffffffu, ab[ti], 4);
    }
    if (jg == 0) {
        #pragma unroll
        for (int ti = 0; ti < 8; ++ti)
            ABARw[4 * ti + sg] = ab[ti] * (1.0f / 32.0f);
    }
    __syncwarp();

    // ================= Phase D': om[s] = sum_d v[s][d] * abar[d] ===========
    {
        float4 ab0 = *(const float4*)(ABARw + dgrp * 8);
        float4 ab1 = *(const float4*)(ABARw + dgrp * 8 + 4);
        __syncwarp();
        float abs_[8] = {ab0.x, ab0.y, ab0.z, ab0.w, ab1.x, ab1.y, ab1.z, ab1.w};
        __half2 ao0 = __float2half2_rn(0.f), ao1 = ao0;
        #pragma unroll
        for (int dd = 0; dd < 8; ++dd) {
            __half2 a2 = __float2half2_rn(abs_[dd]);
            ao0 = __hfma2(acV[0][dd], a2, ao0);
            ao1 = __hfma2(acV[1][dd], a2, ao1);
        }
        float o0 = __low2float(ao0), o1 = __high2float(ao0);
        float o2 = __low2float(ao1), o3 = __high2float(ao1);
        o0 += __shfl_xor_sync(0xffffffffu, o0, 1); o0 += __shfl_xor_sync(0xffffffffu, o0, 2);
        o1 += __shfl_xor_sync(0xffffffffu, o1, 1); o1 += __shfl_xor_sync(0xffffffffu, o1, 2);
        o2 += __shfl_xor_sync(0xffffffffu, o2, 1); o2 += __shfl_xor_sync(0xffffffffu, o2, 2);
        o3 += __shfl_xor_sync(0xffffffffu, o3, 1); o3 += __shfl_xor_sync(0xffffffffu, o3, 2);
        if (dgrp == 0) {
            float4 st; st.x = o0; st.y = o1; st.z = o2; st.w = o3;
            *(float4*)(ABARw + sgrp * 4) = st;    // om overwrites abar
        }
    }
    __syncwarp();

    // ================= Phase F: out = mean_d(x) + f*(Wo*om + bo) ===========
    const float fact = factor[0];
    const float mx0 = sm[OFF_MX + warp * CH + lane];
    const float mx1 = sm[OFF_MX + warp * CH + lane + 32];
    float4 om4[8];
    #pragma unroll
    for (int t = 0; t < 8; ++t) om4[t] = *(const float4*)(ABARw + t * 4);
    float ac0 = 0.f, ac1 = 0.f;
    #pragma unroll
    for (int t = 0; t < 8; ++t) {
        const float* wo = sm + OFF_WOT + (4 * t) * CH + lane;
        ac0 += wo[0]   * om4[t].x;  ac1 += wo[32]  * om4[t].x;
        ac0 += wo[64]  * om4[t].y;  ac1 += wo[96]  * om4[t].y;
        ac0 += wo[128] * om4[t].z;  ac1 += wo[160] * om4[t].z;
        ac0 += wo[192] * om4[t].w;  ac1 += wo[224] * om4[t].w;
    }
    float r0 = mx0 * (1.0f / 32.0f) + fact * (ac0 + sm[OFF_BO + lane]);
    float r1 = mx1 * (1.0f / 32.0f) + fact * (ac1 + sm[OFF_BO + lane + 32]);
    sm[OFF_OUT + lane * 8 + warp]        = r0;
    sm[OFF_OUT + (lane + 32) * 8 + warp] = r1;

    __syncthreads();
    // coalesced output: out[b][c][h][w0..w0+7]
    for (int e = tid; e < CH * WT; e += 256) {
        int c = e >> 3, wl = e & 7;
        out[(((size_t)b * CH + c) * H + h) * W + w0 + wl] = sm[OFF_OUT + e];
    }
}

extern "C" void kernel_launch(void* const* d_in, const int* in_sizes, int n_in,
                              void* d_out, int out_size)
{
    (void)in_sizes; (void)n_in; (void)out_size;
    const float* x      = (const float*)d_in[0];
    const float* Wk     = (const float*)d_in[1];
    const float* bk     = (const float*)d_in[2];
    const float* Wq     = (const float*)d_in[3];
    const float* bq     = (const float*)d_in[4];
    const float* Wv     = (const float*)d_in[5];
    const float* bv     = (const float*)d_in[6];
    const float* Wo     = (const float*)d_in[7];
    const float* bo     = (const float*)d_in[8];
    const float* factor = (const float*)d_in[9];
    float* out = (float*)d_out;

    cudaFuncSetAttribute(attn_fused_kernel,
                         cudaFuncAttributeMaxDynamicSharedMemorySize,
                         (int)SMEM_BYTES);
    dim3 grid(B * H * (W / WT));   // 4096
    dim3 block(256);
    attn_fused_kernel<<<grid, block, SMEM_BYTES>>>(
        x, Wk, bk, Wq, bq, Wv, bv, Wo, bo, factor, out);
}

// round 12
// speedup vs baseline: 1.8688x; 1.8688x over previous
#include <cuda_runtime.h>
#include <cuda_fp16.h>
#include <cstdint>

// ---------------------------------------------------------------------------
// Attention_layer, R11: warp-level tensor cores.
//  - projections k,q,v via mma.sync.m16n8k16 (fp16 in, fp32 accum), fragments
//    loaded with direct conflict-free LDS.32 from [row][col] fp16 layouts
//  - scores via mma.sync on register-transposed (movmatrix) k/q tiles
//  - softmax on fragment layout in two j-halves; abar->fp16; D' = HFMA2 regs
//  - no kT/qT smem; ~64KB smem; 3 CTAs/SM
// ---------------------------------------------------------------------------

__device__ __forceinline__ float ex2(float x) {
    float r; asm("ex2.approx.f32 %0,%1;" : "=f"(r) : "f"(x)); return r;
}
__device__ __forceinline__ void mma16816(float& c0, float& c1, float& c2, float& c3,
                                         uint32_t a0, uint32_t a1, uint32_t a2, uint32_t a3,
                                         uint32_t b0, uint32_t b1)
{
    asm volatile("mma.sync.aligned.m16n8k16.row.col.f32.f16.f16.f32 "
                 "{%0,%1,%2,%3}, {%4,%5,%6,%7}, {%8,%9}, {%0,%1,%2,%3};"
                 : "+f"(c0), "+f"(c1), "+f"(c2), "+f"(c3)
                 : "r"(a0), "r"(a1), "r"(a2), "r"(a3), "r"(b0), "r"(b1));
}
__device__ __forceinline__ uint32_t movm(uint32_t x) {
    uint32_t r; asm volatile("movmatrix.sync.aligned.m8n8.trans.b16 %0, %1;"
                             : "=r"(r) : "r"(x));
    return r;
}
__device__ __forceinline__ uint32_t pack_h2(float a, float b) {
    __half2 h = __floats2half2_rn(a, b);
    return *reinterpret_cast<uint32_t*>(&h);
}

// Problem constants
static constexpr int B  = 8;
static constexpr int CH = 64;
static constexpr int D  = 32;
static constexpr int H  = 64;
static constexpr int W  = 64;
static constexpr int S  = 32;
static constexpr int WT = 8;            // positions (warps) per CTA
static constexpr int HW = H * W;

// fp16 matrix rows padded to 72 halves = 36 words (conflict-free frag loads)
static constexpr int RW   = 36;         // row stride (words) for x / W matrices
static constexpr int UWX  = 1156;       // per-warp x region (words): 32*36 + 4 pad

// smem layout (words)
static constexpr int OFF_U    = 0;                      // 8 * 1156 = 9248
static constexpr int OFF_WKH  = OFF_U + WT * UWX;       // 9248  (32*36 = 1152)
static constexpr int OFF_WQH  = OFF_WKH + 1152;         // 10400
static constexpr int OFF_WVH  = OFF_WQH + 1152;         // 11552
static constexpr int OFF_WOT  = OFF_WVH + 1152;         // 12704 fp32 [s][c] 2048
static constexpr int OFF_BF   = OFF_WOT + S * CH;       // 14752 fp32 bk|bq|bv (96)
static constexpr int OFF_BO   = OFF_BF + 96;            // 14848 (64)
static constexpr int OFF_MX   = OFF_BO + CH;            // 14912 x-mean [w][c] 512
static constexpr int OFF_AB   = OFF_MX + WT * CH;       // 15424 om fp32 8*32
static constexpr int OFF_ABH  = OFF_AB + WT * S;        // 15680 abar fp16 8*16w
static constexpr int OFF_OUT  = OFF_ABH + WT * 16;      // 15808 (512)
static constexpr int SMEM_FLOATS = OFF_OUT + CH * WT;   // 16320
static constexpr size_t SMEM_BYTES = (size_t)SMEM_FLOATS * 4;  // ~63.8 KB

// Projection GEMM: C[2 mt][4 nt] (m16n8k16 accum quads), A = W fp16 [s][c],
// B = x fp16 [d][c] rows (col-major B fragments come from the [n][k] layout).
__device__ __forceinline__ void proj_mma(const uint32_t* __restrict__ Wm,
                                         const uint32_t* __restrict__ xw,
                                         const float* __restrict__ bf,
                                         int g, int t,
                                         float C0[2][4], float C1[2][4],
                                         float C2[2][4], float C3[2][4])
{
    float blo[2], bhi[2];
    #pragma unroll
    for (int mt = 0; mt < 2; ++mt) { blo[mt] = bf[16*mt + g]; bhi[mt] = bf[16*mt + 8 + g]; }
    #pragma unroll
    for (int mt = 0; mt < 2; ++mt)
        #pragma unroll
        for (int nt = 0; nt < 4; ++nt) {
            C0[mt][nt] = blo[mt]; C1[mt][nt] = blo[mt];
            C2[mt][nt] = bhi[mt]; C3[mt][nt] = bhi[mt];
        }
    #pragma unroll
    for (int kt = 0; kt < 4; ++kt) {
        uint32_t a[2][4];
        #pragma unroll
        for (int mt = 0; mt < 2; ++mt) {
            int base = (16*mt + g) * RW + 8*kt + t;
            a[mt][0] = Wm[base];
            a[mt][1] = Wm[base + 8*RW];   // row + 8
            a[mt][2] = Wm[base + 4];      // col + 8 (halves) = +4 words
            a[mt][3] = Wm[base + 8*RW + 4];
        }
        #pragma unroll
        for (int nt = 0; nt < 4; ++nt) {
            int bb = (8*nt + g) * RW + 8*kt + t;
            uint32_t b0 = xw[bb], b1 = xw[bb + 4];
            #pragma unroll
            for (int mt = 0; mt < 2; ++mt)
                mma16816(C0[mt][nt], C1[mt][nt], C2[mt][nt], C3[mt][nt],
                         a[mt][0], a[mt][1], a[mt][2], a[mt][3], b0, b1);
        }
    }
}

__global__ __launch_bounds__(256, 3)
void attn_fused_kernel(const float* __restrict__ x,
                       const float* __restrict__ Wk, const float* __restrict__ bk,
                       const float* __restrict__ Wq, const float* __restrict__ bq,
                       const float* __restrict__ Wv, const float* __restrict__ bv,
                       const float* __restrict__ Wo, const float* __restrict__ bo,
                       const float* __restrict__ factor,
                       float* __restrict__ out)
{
    extern __shared__ float sm[];
    const int tid  = threadIdx.x;
    const int blk  = blockIdx.x;
    const int b    = blk >> 9;
    const int rem  = blk & 511;
    const int h    = rem >> 3;
    const int w0   = (rem & 7) << 3;

    // ---- Stage x: thread = (c, w-pair); fp32 mean in regs; x -> fp16 [d][c]
    {
        const int c  = tid >> 2;          // 0..63
        const int wp = (tid & 3) << 1;    // 0,2,4,6
        const float* bi = x + ((size_t)b * CH * D + (size_t)c * D) * HW + h * W + w0 + wp;
        __half* xhA = (__half*)(sm + OFF_U + (size_t)wp * UWX);
        __half* xhB = (__half*)(sm + OFF_U + (size_t)(wp + 1) * UWX);
        float msA = 0.f, msB = 0.f;
        #pragma unroll 8
        for (int d = 0; d < D; ++d) {
            float2 v = *(const float2*)(bi + (size_t)d * HW);
            msA += v.x; msB += v.y;
            xhA[d * 2 * RW + c] = __float2half_rn(v.x);
            xhB[d * 2 * RW + c] = __float2half_rn(v.y);
        }
        sm[OFF_MX + wp * CH + c]       = msA;
        sm[OFF_MX + (wp + 1) * CH + c] = msB;
    }

    // ---- Stage weights: Wk/Wq/Wv fp16 [s][c], rows padded to 36 words ----
    {
        __half2* wkh = (__half2*)(sm + OFF_WKH);
        __half2* wqh = (__half2*)(sm + OFF_WQH);
        __half2* wvh = (__half2*)(sm + OFF_WVH);
        for (int i = tid; i < 1024; i += 256) {
            int s = i >> 5, cp = i & 31;
            float2 vk = *(const float2*)(Wk + s * CH + 2 * cp);
            float2 vq = *(const float2*)(Wq + s * CH + 2 * cp);
            float2 vv = *(const float2*)(Wv + s * CH + 2 * cp);
            wkh[s * RW + cp] = __floats2half2_rn(vk.x, vk.y);
            wqh[s * RW + cp] = __floats2half2_rn(vq.x, vq.y);
            wvh[s * RW + cp] = __floats2half2_rn(vv.x, vv.y);
        }
    }
    // Wo fp32 [s][c]
    for (int i = tid; i < CH * S; i += 256) {
        int s2 = i >> 6, c2 = i & 63;
        sm[OFF_WOT + i] = Wo[c2 * S + s2];
    }
    // fp32 biases bk|bq|bv
    if (tid < 96) {
        int m = tid >> 5, tt = tid & 31;
        const float* src = (m == 0) ? bk : ((m == 1) ? bq : bv);
        sm[OFF_BF + tid] = src[tt];
    }
    if (tid < CH) sm[OFF_BO + tid] = bo[tid];
    __syncthreads();

    const int warp = tid >> 5;
    const int lane = tid & 31;
    const int g    = lane >> 2;   // 0..7 (mma group)
    const int t    = lane & 3;    // 0..3 (mma thread-in-group)

    const uint32_t* xw32 = (const uint32_t*)(sm + OFF_U + warp * UWX);
    const uint32_t* Wk32 = (const uint32_t*)(sm + OFF_WKH);
    const uint32_t* Wq32 = (const uint32_t*)(sm + OFF_WQH);
    const uint32_t* Wv32 = (const uint32_t*)(sm + OFF_WVH);
    const float*    bF   = sm + OFF_BF;
    float* ABARw = sm + OFF_AB + warp * S;
    __half* abh  = (__half*)(sm + OFF_ABH + warp * 16);

    float C0[2][4], C1[2][4], C2[2][4], C3[2][4];

    // ---- V projection (accum stays in fp16 regs for D') ----
    proj_mma(Wv32, xw32, bF + 64, g, t, C0, C1, C2, C3);
    __half2 vh[2][2][4];                 // [hi/lo s-half][mt][nt], d-pair packed
    #pragma unroll
    for (int mt = 0; mt < 2; ++mt)
        #pragma unroll
        for (int nt = 0; nt < 4; ++nt) {
            uint32_t lo = pack_h2(C0[mt][nt], C1[mt][nt]);
            uint32_t hi = pack_h2(C2[mt][nt], C3[mt][nt]);
            vh[0][mt][nt] = *reinterpret_cast<__half2*>(&lo);
            vh[1][mt][nt] = *reinterpret_cast<__half2*>(&hi);
        }

    // ---- Q projection -> transposed fragments QT[sb][db] via movmatrix ----
    proj_mma(Wq32, xw32, bF + 32, g, t, C0, C1, C2, C3);
    uint32_t QT[4][4];
    #pragma unroll
    for (int mt = 0; mt < 2; ++mt)
        #pragma unroll
        for (int nt = 0; nt < 4; ++nt) {
            QT[2*mt][nt]     = movm(pack_h2(C0[mt][nt], C1[mt][nt]));
            QT[2*mt + 1][nt] = movm(pack_h2(C2[mt][nt], C3[mt][nt]));
        }

    // ---- K projection -> KT[sb][db] ----
    proj_mma(Wk32, xw32, bF, g, t, C0, C1, C2, C3);
    uint32_t KT[4][4];
    #pragma unroll
    for (int mt = 0; mt < 2; ++mt)
        #pragma unroll
        for (int nt = 0; nt < 4; ++nt) {
            KT[2*mt][nt]     = movm(pack_h2(C0[mt][nt], C1[mt][nt]));
            KT[2*mt + 1][nt] = movm(pack_h2(C2[mt][nt], C3[mt][nt]));
        }

    // ---- Scores + softmax + abar, in two j-halves ----
    const float CEXP = 0.17677669529663687f * 1.44269504088896340f;
    float ab0 = 0.f, ab1 = 0.f, ab2 = 0.f, ab3 = 0.f;   // i = g, g+8, g+16, g+24

    #pragma unroll
    for (int hf = 0; hf < 2; ++hf) {
        float S0[2][2], S1[2][2], S2[2][2], S3[2][2];
        #pragma unroll
        for (int mt = 0; mt < 2; ++mt)
            #pragma unroll
            for (int nl = 0; nl < 2; ++nl) {
                S0[mt][nl] = 0.f; S1[mt][nl] = 0.f; S2[mt][nl] = 0.f; S3[mt][nl] = 0.f;
            }
        #pragma unroll
        for (int kt = 0; kt < 2; ++kt)
            #pragma unroll
            for (int mt = 0; mt < 2; ++mt) {
                uint32_t a0 = KT[2*kt][2*mt],   a1 = KT[2*kt][2*mt + 1];
                uint32_t a2 = KT[2*kt+1][2*mt], a3 = KT[2*kt+1][2*mt + 1];
                #pragma unroll
                for (int nl = 0; nl < 2; ++nl) {
                    int ntj = 2*hf + nl;
                    mma16816(S0[mt][nl], S1[mt][nl], S2[mt][nl], S3[mt][nl],
                             a0, a1, a2, a3, QT[2*kt][ntj], QT[2*kt+1][ntj]);
                }
            }
        // softmax over i for this lane's 4 columns (2 nl x 2 parity)
        #pragma unroll
        for (int nl = 0; nl < 2; ++nl)
            #pragma unroll
            for (int p = 0; p < 2; ++p) {
                float f0 = p ? S1[0][nl] : S0[0][nl];   // i = g
                float f1 = p ? S3[0][nl] : S2[0][nl];   // i = g+8
                float f2 = p ? S1[1][nl] : S0[1][nl];   // i = g+16
                float f3 = p ? S3[1][nl] : S2[1][nl];   // i = g+24
                float m = fmaxf(fmaxf(f0, f1), fmaxf(f2, f3));
                m = fmaxf(m, __shfl_xor_sync(0xffffffffu, m, 4));
                m = fmaxf(m, __shfl_xor_sync(0xffffffffu, m, 8));
                m = fmaxf(m, __shfl_xor_sync(0xffffffffu, m, 16));
                float e0 = ex2((f0 - m) * CEXP);
                float e1 = ex2((f1 - m) * CEXP);
                float e2 = ex2((f2 - m) * CEXP);
                float e3 = ex2((f3 - m) * CEXP);
                float su = (e0 + e1) + (e2 + e3);
                su += __shfl_xor_sync(0xffffffffu, su, 4);
                su += __shfl_xor_sync(0xffffffffu, su, 8);
                su += __shfl_xor_sync(0xffffffffu, su, 16);
                float r = 1.0f / su;
                ab0 += e0 * r; ab1 += e1 * r; ab2 += e2 * r; ab3 += e3 * r;
            }
    }
    // abar[i] = mean over j: reduce over t lanes, scale by 1/32
    ab0 += __shfl_xor_sync(0xffffffffu, ab0, 1); ab0 += __shfl_xor_sync(0xffffffffu, ab0, 2);
    ab1 += __shfl_xor_sync(0xffffffffu, ab1, 1); ab1 += __shfl_xor_sync(0xffffffffu, ab1, 2);
    ab2 += __shfl_xor_sync(0xffffffffu, ab2, 1); ab2 += __shfl_xor_sync(0xffffffffu, ab2, 2);
    ab3 += __shfl_xor_sync(0xffffffffu, ab3, 1); ab3 += __shfl_xor_sync(0xffffffffu, ab3, 2);
    if (t == 0) {
        abh[g]      = __float2half_rn(ab0 * (1.0f / 32.0f));
        abh[g + 8]  = __float2half_rn(ab1 * (1.0f / 32.0f));
        abh[g + 16] = __float2half_rn(ab2 * (1.0f / 32.0f));
        abh[g + 24] = __float2half_rn(ab3 * (1.0f / 32.0f));
    }
    __syncwarp();

    // ---- D': om[s] = sum_d v[s][d] * abar[d] (HFMA2 on register v) ----
    {
        const uint32_t* abw = (const uint32_t*)abh;
        uint32_t ab2w[4];
        #pragma unroll
        for (int nt = 0; nt < 4; ++nt) ab2w[nt] = abw[4*nt + t];  // (abar[8nt+2t], +1)
        __syncwarp();
        #pragma unroll
        for (int mt = 0; mt < 2; ++mt)
            #pragma unroll
            for (int hh = 0; hh < 2; ++hh) {
                __half2 acc = __float2half2_rn(0.f);
                #pragma unroll
                for (int nt = 0; nt < 4; ++nt)
                    acc = __hfma2(vh[hh][mt][nt], *reinterpret_cast<__half2*>(&ab2w[nt]), acc);
                float os = __low2float(acc) + __high2float(acc);
                os += __shfl_xor_sync(0xffffffffu, os, 1);
                os += __shfl_xor_sync(0xffffffffu, os, 2);
                if (t == 0) ABARw[16*mt + 8*hh + g] = os;
            }
    }
    __syncwarp();

    // ---- Phase F: out = mean_d(x) + f*(Wo*om + bo) ----
    const float fact = factor[0];
    const float mx0 = sm[OFF_MX + warp * CH + lane];
    const float mx1 = sm[OFF_MX + warp * CH + lane + 32];
    float4 om4[8];
    #pragma unroll
    for (int u = 0; u < 8; ++u) om4[u] = *(const float4*)(ABARw + u * 4);
    float ac0 = 0.f, ac1 = 0.f;
    #pragma unroll
    for (int u = 0; u < 8; ++u) {
        const float* wo = sm + OFF_WOT + (4 * u) * CH + lane;
        ac0 += wo[0]   * om4[u].x;  ac1 += wo[32]  * om4[u].x;
        ac0 += wo[64]  * om4[u].y;  ac1 += wo[96]  * om4[u].y;
        ac0 += wo[128] * om4[u].z;  ac1 += wo[160] * om4[u].z;
        ac0 += wo[192] * om4[u].w;  ac1 += wo[224] * om4[u].w;
    }
    float r0 = mx0 * (1.0f / 32.0f) + fact * (ac0 + sm[OFF_BO + lane]);
    float r1 = mx1 * (1.0f / 32.0f) + fact * (ac1 + sm[OFF_BO + lane + 32]);
    sm[OFF_OUT + lane * 8 + warp]        = r0;
    sm[OFF_OUT + (lane + 32) * 8 + warp] = r1;

    __syncthreads();
    // coalesced output: out[b][c][h][w0..w0+7]
    for (int e = tid; e < CH * WT; e += 256) {
        int c = e >> 3, wl = e & 7;
        out[(((size_t)b * CH + c) * H + h) * W + w0 + wl] = sm[OFF_OUT + e];
    }
}

extern "C" void kernel_launch(void* const* d_in, const int* in_sizes, int n_in,
                              void* d_out, int out_size)
{
    (void)in_sizes; (void)n_in; (void)out_size;
    const float* x      = (const float*)d_in[0];
    const float* Wk     = (const float*)d_in[1];
    const float* bk     = (const float*)d_in[2];
    const float* Wq     = (const float*)d_in[3];
    const float* bq     = (const float*)d_in[4];
    const float* Wv     = (const float*)d_in[5];
    const float* bv     = (const float*)d_in[6];
    const float* Wo     = (const float*)d_in[7];
    const float* bo     = (const float*)d_in[8];
    const float* factor = (const float*)d_in[9];
    float* out = (float*)d_out;

    cudaFuncSetAttribute(attn_fused_kernel,
                         cudaFuncAttributeMaxDynamicSharedMemorySize,
                         (int)SMEM_BYTES);
    dim3 grid(B * H * (W / WT));   // 4096
    dim3 block(256);
    attn_fused_kernel<<<grid, block, SMEM_BYTES>>>(
        x, Wk, bk, Wq, bq, Wv, bv, Wo, bo, factor, out);
}

// round 13
// speedup vs baseline: 1.9523x; 1.0447x over previous
#include <cuda_runtime.h>
#include <cuda_fp16.h>
#include <cstdint>

// ---------------------------------------------------------------------------
// Attention_layer, R12: tensor-core path with vectorized fragment feeds.
//  - weights staged in A-fragment order -> 1 LDS.128 per (kt,mt)
//  - x staged in b-frag permuted cols (row stride 40w, conflict-free LDS.64)
//  - scores on movmatrix-transposed register tiles (no smem)
//  - Wo fp16 s-pair packed; om fp16; phase F HFMA2
// ---------------------------------------------------------------------------

__device__ __forceinline__ float ex2(float x) {
    float r; asm("ex2.approx.f32 %0,%1;" : "=f"(r) : "f"(x)); return r;
}
__device__ __forceinline__ void mma16816(float& c0, float& c1, float& c2, float& c3,
                                         uint32_t a0, uint32_t a1, uint32_t a2, uint32_t a3,
                                         uint32_t b0, uint32_t b1)
{
    asm volatile("mma.sync.aligned.m16n8k16.row.col.f32.f16.f16.f32 "
                 "{%0,%1,%2,%3}, {%4,%5,%6,%7}, {%8,%9}, {%0,%1,%2,%3};"
                 : "+f"(c0), "+f"(c1), "+f"(c2), "+f"(c3)
                 : "r"(a0), "r"(a1), "r"(a2), "r"(a3), "r"(b0), "r"(b1));
}
__device__ __forceinline__ uint32_t movm(uint32_t x) {
    uint32_t r; asm volatile("movmatrix.sync.aligned.m8n8.trans.b16 %0, %1;"
                             : "=r"(r) : "r"(x));
    return r;
}
__device__ __forceinline__ uint32_t pack_h2(float a, float b) {
    __half2 h = __floats2half2_rn(a, b);
    return *reinterpret_cast<uint32_t*>(&h);
}

// Problem constants
static constexpr int B  = 8;
static constexpr int CH = 64;
static constexpr int D  = 32;
static constexpr int H  = 64;
static constexpr int W  = 64;
static constexpr int S  = 32;
static constexpr int WT = 8;
static constexpr int HW = H * W;

static constexpr int XRW  = 40;         // x row stride (words); bank-spread 8g
static constexpr int UWX  = 1284;       // per-warp x region words (1280 + pad)

// smem layout (words)
static constexpr int OFF_U    = 0;                      // 8*1284 = 10272
static constexpr int OFF_WKF  = OFF_U + WT * UWX;       // A-frag order, 1024 w
static constexpr int OFF_WQF  = OFF_WKF + 1024;
static constexpr int OFF_WVF  = OFF_WQF + 1024;
static constexpr int OFF_WOH  = OFF_WVF + 1024;         // fp16 [sp][c] 1024 w
static constexpr int OFF_BF   = OFF_WOH + 1024;         // fp32 bk|bq|bv 96
static constexpr int OFF_BO   = OFF_BF + 96;            // 64
static constexpr int OFF_MX   = OFF_BO + CH;            // x-mean [w][c] 512
static constexpr int OFF_ABH  = OFF_MX + WT * CH;       // abar fp16: 8*16 w
static constexpr int OFF_OMH  = OFF_ABH + WT * 16;      // om fp16: 8*16 w
static constexpr int OFF_OUT  = OFF_OMH + WT * 16;      // 512
static constexpr int SMEM_FLOATS = OFF_OUT + CH * WT;   // 15808
static constexpr size_t SMEM_BYTES = (size_t)SMEM_FLOATS * 4;  // ~61.8 KB

// Projection GEMM with fragment-order operands.
__device__ __forceinline__ void proj_mma(const uint4* __restrict__ Wf,
                                         const uint32_t* __restrict__ xw,
                                         const float* __restrict__ bf,
                                         int lane, int g, int t,
                                         float C0[2][4], float C1[2][4],
                                         float C2[2][4], float C3[2][4])
{
    float blo[2], bhi[2];
    #pragma unroll
    for (int mt = 0; mt < 2; ++mt) { blo[mt] = bf[16*mt + g]; bhi[mt] = bf[16*mt + 8 + g]; }
    #pragma unroll
    for (int mt = 0; mt < 2; ++mt)
        #pragma unroll
        for (int nt = 0; nt < 4; ++nt) {
            C0[mt][nt] = blo[mt]; C1[mt][nt] = blo[mt];
            C2[mt][nt] = bhi[mt]; C3[mt][nt] = bhi[mt];
        }
    #pragma unroll
    for (int kt = 0; kt < 4; ++kt) {
        uint4 a0 = Wf[(kt * 2 + 0) * 32 + lane];
        uint4 a1 = Wf[(kt * 2 + 1) * 32 + lane];
        #pragma unroll
        for (int nt = 0; nt < 4; ++nt) {
            uint2 bb = *(const uint2*)(xw + (8 * nt + g) * XRW + kt * 8 + 2 * t);
            mma16816(C0[0][nt], C1[0][nt], C2[0][nt], C3[0][nt],
                     a0.x, a0.y, a0.z, a0.w, bb.x, bb.y);
            mma16816(C0[1][nt], C1[1][nt], C2[1][nt], C3[1][nt],
                     a1.x, a1.y, a1.z, a1.w, bb.x, bb.y);
        }
    }
}

__global__ __launch_bounds__(256, 3)
void attn_fused_kernel(const float* __restrict__ x,
                       const float* __restrict__ Wk, const float* __restrict__ bk,
                       const float* __restrict__ Wq, const float* __restrict__ bq,
                       const float* __restrict__ Wv, const float* __restrict__ bv,
                       const float* __restrict__ Wo, const float* __restrict__ bo,
                       const float* __restrict__ factor,
                       float* __restrict__ out)
{
    extern __shared__ float sm[];
    const int tid  = threadIdx.x;
    const int blk  = blockIdx.x;
    const int b    = blk >> 9;
    const int rem  = blk & 511;
    const int h    = rem >> 3;
    const int w0   = (rem & 7) << 3;

    // ---- Stage x: thread = (c, w-pair); fp32 mean in regs;
    //      x -> fp16 [d][col'] with b-frag column permutation ----
    {
        const int c  = tid >> 2;          // 0..63
        const int wp = (tid & 3) << 1;    // 0,2,4,6
        const float* bi = x + ((size_t)b * CH * D + (size_t)c * D) * HW + h * W + w0 + wp;
        __half* xhA = (__half*)(sm + OFF_U + (size_t)wp * UWX);
        __half* xhB = (__half*)(sm + OFF_U + (size_t)(wp + 1) * UWX);
        const int wc   = c >> 1;
        const int colp = ((wc >> 3) << 3) | ((wc & 3) << 1) | ((wc >> 2) & 1);
        const int hoff = colp * 2 + (c & 1);
        float msA = 0.f, msB = 0.f;
        #pragma unroll 8
        for (int d = 0; d < D; ++d) {
            float2 v = *(const float2*)(bi + (size_t)d * HW);
            msA += v.x; msB += v.y;
            xhA[d * (2 * XRW) + hoff] = __float2half_rn(v.x);
            xhB[d * (2 * XRW) + hoff] = __float2half_rn(v.y);
        }
        sm[OFF_MX + wp * CH + c]       = msA;
        sm[OFF_MX + (wp + 1) * CH + c] = msB;
    }

    // ---- Stage Wk/Wq/Wv in A-fragment order ----
    {
        uint32_t* wkf = (uint32_t*)(sm + OFF_WKF);
        uint32_t* wqf = (uint32_t*)(sm + OFF_WQF);
        uint32_t* wvf = (uint32_t*)(sm + OFF_WVF);
        for (int i = tid; i < 1024; i += 256) {
            int s = i >> 5, wc = i & 31;
            int kt = wc >> 3, tt = wc & 3, r2 = (wc >> 2) & 1;
            int mt = s >> 4, gg = s & 7, r1 = (s >> 3) & 1;
            int addr = ((kt * 2 + mt) * 32 + gg * 4 + tt) * 4 + r1 + 2 * r2;
            float2 vk = *(const float2*)(Wk + s * CH + 2 * wc);
            float2 vq = *(const float2*)(Wq + s * CH + 2 * wc);
            float2 vv = *(const float2*)(Wv + s * CH + 2 * wc);
            wkf[addr] = pack_h2(vk.x, vk.y);
            wqf[addr] = pack_h2(vq.x, vq.y);
            wvf[addr] = pack_h2(vv.x, vv.y);
        }
    }
    // ---- Wo fp16 [sp][c] (s-pair packed) ----
    {
        uint32_t* woh = (uint32_t*)(sm + OFF_WOH);
        for (int i = tid; i < 1024; i += 256) {
            int sp = i >> 6, c2 = i & 63;
            float2 vw = *(const float2*)(Wo + c2 * S + 2 * sp);
            woh[sp * 64 + c2] = pack_h2(vw.x, vw.y);
        }
    }
    if (tid < 96) {
        int m = tid >> 5, tt = tid & 31;
        const float* src = (m == 0) ? bk : ((m == 1) ? bq : bv);
        sm[OFF_BF + tid] = src[tt];
    }
    if (tid < CH) sm[OFF_BO + tid] = bo[tid];
    __syncthreads();

    const int warp = tid >> 5;
    const int lane = tid & 31;
    const int g    = lane >> 2;   // 0..7
    const int t    = lane & 3;    // 0..3

    const uint32_t* xw32 = (const uint32_t*)(sm + OFF_U + warp * UWX);
    const uint4* WkF = (const uint4*)(sm + OFF_WKF);
    const uint4* WqF = (const uint4*)(sm + OFF_WQF);
    const uint4* WvF = (const uint4*)(sm + OFF_WVF);
    const float* bF  = sm + OFF_BF;
    __half* abh  = (__half*)(sm + OFF_ABH) + warp * 32;
    __half* omh  = (__half*)(sm + OFF_OMH) + warp * 32;

    float C0[2][4], C1[2][4], C2[2][4], C3[2][4];

    // ---- V projection (accum packed to fp16 regs for D') ----
    proj_mma(WvF, xw32, bF + 64, lane, g, t, C0, C1, C2, C3);
    __half2 vh[2][2][4];                 // [s-half (row+8hh)][mt][nt]
    #pragma unroll
    for (int mt = 0; mt < 2; ++mt)
        #pragma unroll
        for (int nt = 0; nt < 4; ++nt) {
            uint32_t lo = pack_h2(C0[mt][nt], C1[mt][nt]);
            uint32_t hi = pack_h2(C2[mt][nt], C3[mt][nt]);
            vh[0][mt][nt] = *reinterpret_cast<__half2*>(&lo);
            vh[1][mt][nt] = *reinterpret_cast<__half2*>(&hi);
        }

    // ---- Q projection -> transposed fragments via movmatrix ----
    proj_mma(WqF, xw32, bF + 32, lane, g, t, C0, C1, C2, C3);
    uint32_t QT[4][4];
    #pragma unroll
    for (int mt = 0; mt < 2; ++mt)
        #pragma unroll
        for (int nt = 0; nt < 4; ++nt) {
            QT[2*mt][nt]     = movm(pack_h2(C0[mt][nt], C1[mt][nt]));
            QT[2*mt + 1][nt] = movm(pack_h2(C2[mt][nt], C3[mt][nt]));
        }

    // ---- K projection -> transposed fragments ----
    proj_mma(WkF, xw32, bF, lane, g, t, C0, C1, C2, C3);
    uint32_t KT[4][4];
    #pragma unroll
    for (int mt = 0; mt < 2; ++mt)
        #pragma unroll
        for (int nt = 0; nt < 4; ++nt) {
            KT[2*mt][nt]     = movm(pack_h2(C0[mt][nt], C1[mt][nt]));
            KT[2*mt + 1][nt] = movm(pack_h2(C2[mt][nt], C3[mt][nt]));
        }

    // ---- Scores + softmax + abar, in two j-halves ----
    const float CEXP = 0.17677669529663687f * 1.44269504088896340f;
    float ab0 = 0.f, ab1 = 0.f, ab2 = 0.f, ab3 = 0.f;   // i = g, g+8, g+16, g+24

    #pragma unroll
    for (int hf = 0; hf < 2; ++hf) {
        float S0[2][2], S1[2][2], S2[2][2], S3[2][2];
        #pragma unroll
        for (int mt = 0; mt < 2; ++mt)
            #pragma unroll
            for (int nl = 0; nl < 2; ++nl) {
                S0[mt][nl] = 0.f; S1[mt][nl] = 0.f; S2[mt][nl] = 0.f; S3[mt][nl] = 0.f;
            }
        #pragma unroll
        for (int kt = 0; kt < 2; ++kt)
            #pragma unroll
            for (int mt = 0; mt < 2; ++mt) {
                uint32_t a0 = KT[2*kt][2*mt],   a1 = KT[2*kt][2*mt + 1];
                uint32_t a2 = KT[2*kt+1][2*mt], a3 = KT[2*kt+1][2*mt + 1];
                #pragma unroll
                for (int nl = 0; nl < 2; ++nl) {
                    int ntj = 2*hf + nl;
                    mma16816(S0[mt][nl], S1[mt][nl], S2[mt][nl], S3[mt][nl],
                             a0, a1, a2, a3, QT[2*kt][ntj], QT[2*kt+1][ntj]);
                }
            }
        #pragma unroll
        for (int nl = 0; nl < 2; ++nl)
            #pragma unroll
            for (int p = 0; p < 2; ++p) {
                float f0 = p ? S1[0][nl] : S0[0][nl];
                float f1 = p ? S3[0][nl] : S2[0][nl];
                float f2 = p ? S1[1][nl] : S0[1][nl];
                float f3 = p ? S3[1][nl] : S2[1][nl];
                float m = fmaxf(fmaxf(f0, f1), fmaxf(f2, f3));
                m = fmaxf(m, __shfl_xor_sync(0xffffffffu, m, 4));
                m = fmaxf(m, __shfl_xor_sync(0xffffffffu, m, 8));
                m = fmaxf(m, __shfl_xor_sync(0xffffffffu, m, 16));
                float e0 = ex2((f0 - m) * CEXP);
                float e1 = ex2((f1 - m) * CEXP);
                float e2 = ex2((f2 - m) * CEXP);
                float e3 = ex2((f3 - m) * CEXP);
                float su = (e0 + e1) + (e2 + e3);
                su += __shfl_xor_sync(0xffffffffu, su, 4);
                su += __shfl_xor_sync(0xffffffffu, su, 8);
                su += __shfl_xor_sync(0xffffffffu, su, 16);
                float r = 1.0f / su;
                ab0 += e0 * r; ab1 += e1 * r; ab2 += e2 * r; ab3 += e3 * r;
            }
    }
    ab0 += __shfl_xor_sync(0xffffffffu, ab0, 1); ab0 += __shfl_xor_sync(0xffffffffu, ab0, 2);
    ab1 += __shfl_xor_sync(0xffffffffu, ab1, 1); ab1 += __shfl_xor_sync(0xffffffffu, ab1, 2);
    ab2 += __shfl_xor_sync(0xffffffffu, ab2, 1); ab2 += __shfl_xor_sync(0xffffffffu, ab2, 2);
    ab3 += __shfl_xor_sync(0xffffffffu, ab3, 1); ab3 += __shfl_xor_sync(0xffffffffu, ab3, 2);
    if (t == 0) {
        abh[g]      = __float2half_rn(ab0 * (1.0f / 32.0f));
        abh[g + 8]  = __float2half_rn(ab1 * (1.0f / 32.0f));
        abh[g + 16] = __float2half_rn(ab2 * (1.0f / 32.0f));
        abh[g + 24] = __float2half_rn(ab3 * (1.0f / 32.0f));
    }
    __syncwarp();

    // ---- D': om[s] = sum_d v[s][d] * abar[d] (HFMA2 on register v) ----
    {
        const uint32_t* abw = (const uint32_t*)abh;
        uint32_t ab2w[4];
        #pragma unroll
        for (int nt = 0; nt < 4; ++nt) ab2w[nt] = abw[4*nt + t];
        __syncwarp();
        #pragma unroll
        for (int mt = 0; mt < 2; ++mt)
            #pragma unroll
            for (int hh = 0; hh < 2; ++hh) {
                __half2 acc = __float2half2_rn(0.f);
                #pragma unroll
                for (int nt = 0; nt < 4; ++nt)
                    acc = __hfma2(vh[hh][mt][nt], *reinterpret_cast<__half2*>(&ab2w[nt]), acc);
                float os = __low2float(acc) + __high2float(acc);
                os += __shfl_xor_sync(0xffffffffu, os, 1);
                os += __shfl_xor_sync(0xffffffffu, os, 2);
                if (t == 0) omh[16*mt + 8*hh + g] = __float2half_rn(os);
            }
    }
    __syncwarp();

    // ---- Phase F: out = mean_d(x) + f*(Wo*om + bo), Wo fp16 ----
    const float fact = factor[0];
    const float mx0 = sm[OFF_MX + warp * CH + lane];
    const float mx1 = sm[OFF_MX + warp * CH + lane + 32];
    uint4 omq[4];
    #pragma unroll
    for (int u = 0; u < 4; ++u) omq[u] = ((const uint4*)omh)[u];
    const uint32_t* woh = (const uint32_t*)(sm + OFF_WOH);
    __half2 a0h = __float2half2_rn(0.f), a1h = a0h;
    #pragma unroll
    for (int sp = 0; sp < 16; ++sp) {
        uint32_t omw = ((const uint32_t*)&omq[sp >> 2])[sp & 3];
        __half2 om2 = *reinterpret_cast<__half2*>(&omw);
        uint32_t w0 = woh[sp * 64 + lane];
        uint32_t w1 = woh[sp * 64 + lane + 32];
        a0h = __hfma2(*reinterpret_cast<__half2*>(&w0), om2, a0h);
        a1h = __hfma2(*reinterpret_cast<__half2*>(&w1), om2, a1h);
    }
    float ac0 = __low2float(a0h) + __high2float(a0h);
    float ac1 = __low2float(a1h) + __high2float(a1h);
    float r0 = mx0 * (1.0f / 32.0f) + fact * (ac0 + sm[OFF_BO + lane]);
    float r1 = mx1 * (1.0f / 32.0f) + fact * (ac1 + sm[OFF_BO + lane + 32]);
    sm[OFF_OUT + lane * 8 + warp]        = r0;
    sm[OFF_OUT + (lane + 32) * 8 + warp] = r1;

    __syncthreads();
    for (int e = tid; e < CH * WT; e += 256) {
        int c = e >> 3, wl = e & 7;
        out[(((size_t)b * CH + c) * H + h) * W + w0 + wl] = sm[OFF_OUT + e];
    }
}

extern "C" void kernel_launch(void* const* d_in, const int* in_sizes, int n_in,
                              void* d_out, int out_size)
{
    (void)in_sizes; (void)n_in; (void)out_size;
    const float* x      = (const float*)d_in[0];
    const float* Wk     = (const float*)d_in[1];
    const float* bk     = (const float*)d_in[2];
    const float* Wq     = (const float*)d_in[3];
    const float* bq     = (const float*)d_in[4];
    const float* Wv     = (const float*)d_in[5];
    const float* bv     = (const float*)d_in[6];
    const float* Wo     = (const float*)d_in[7];
    const float* bo     = (const float*)d_in[8];
    const float* factor = (const float*)d_in[9];
    float* out = (float*)d_out;

    cudaFuncSetAttribute(attn_fused_kernel,
                         cudaFuncAttributeMaxDynamicSharedMemorySize,
                         (int)SMEM_BYTES);
    dim3 grid(B * H * (W / WT));   // 4096
    dim3 block(256);
    attn_fused_kernel<<<grid, block, SMEM_BYTES>>>(
        x, Wk, bk, Wq, bq, Wv, bv, Wo, bo, factor, out);
}